// round 9
// baseline (speedup 1.0000x reference)
#include <cuda_runtime.h>
#include <math.h>

#define BATCH 2048
#define NC    9605
#define NL    8
#define MAXWL 512
#define NTHR  256
#define CAP   2048    // candidate cap; shares smem with fallback histogram

__device__ int           g_wl_count;   // 0-init; reset by last block each launch
__device__ int           g_wl_idx[MAXWL];
__device__ unsigned char g_wl_mask[MAXWL];
__device__ float         g_row_val[BATCH];
__device__ int           g_done;       // 0-init; reset each launch
__device__ int           g_wl_ready;   // 0-init; reset each launch

__device__ __forceinline__ float sigmoidf_(float v) {
    return 1.0f / (1.0f + expf(-v));   // v = -1e30 -> 0 (correct)
}
__device__ __forceinline__ unsigned f2k(unsigned u) {          // monotone float->uint
    return (u & 0x80000000u) ? ~u : (u | 0x80000000u);
}
__device__ __forceinline__ float k2f(unsigned k) {
    return (k & 0x80000000u) ? __uint_as_float(k ^ 0x80000000u)
                             : __uint_as_float(~k);
}

// pick8: suffix-select over 2048 bins (thread t owns bins [8t,8t+8)). (fallback)
__device__ __forceinline__ void pick8(const unsigned* __restrict__ hist,
                                      unsigned* __restrict__ wsum,
                                      unsigned* __restrict__ sb,
                                      unsigned* __restrict__ sw,
                                      unsigned* __restrict__ sc,
                                      unsigned want, int tid) {
    unsigned v[8];
    unsigned tot = 0;
#pragma unroll
    for (int i = 0; i < 8; ++i) { v[i] = hist[tid * 8 + i]; tot += v[i]; }
    unsigned incl = tot;
#pragma unroll
    for (int d = 1; d < 32; d <<= 1) {
        unsigned n = __shfl_down_sync(0xffffffffu, incl, d);
        if ((tid & 31) + d < 32) incl += n;
    }
    if ((tid & 31) == 0) wsum[tid >> 5] = incl;
    __syncthreads();
    unsigned above = incl - tot;
#pragma unroll
    for (int w = 0; w < NTHR / 32; ++w)
        if (w > (tid >> 5)) above += wsum[w];
    unsigned suf = above;
#pragma unroll
    for (int j = 7; j >= 0; --j) {
        unsigned nsuf = suf + v[j];
        if (suf < want && want <= nsuf) {
            *sb = (unsigned)(tid * 8 + j); *sw = want - suf; *sc = v[j];
        }
        suf = nsuf;
    }
    __syncthreads();
}

// pick1: suffix-select over <=256 bins (thread t owns bin t). (fallback)
__device__ __forceinline__ void pick1(const unsigned* __restrict__ hist, int nbins,
                                      unsigned* __restrict__ wsum,
                                      unsigned* __restrict__ sb,
                                      unsigned* __restrict__ sw,
                                      unsigned* __restrict__ sc,
                                      unsigned want, int tid) {
    unsigned v = (tid < nbins) ? hist[tid] : 0u;
    unsigned incl = v;
#pragma unroll
    for (int d = 1; d < 32; d <<= 1) {
        unsigned n = __shfl_down_sync(0xffffffffu, incl, d);
        if ((tid & 31) + d < 32) incl += n;
    }
    if ((tid & 31) == 0) wsum[tid >> 5] = incl;
    __syncthreads();
    unsigned above = incl - v;
#pragma unroll
    for (int w = 0; w < NTHR / 32; ++w)
        if (w > (tid >> 5)) above += wsum[w];
    if (above < want && want <= above + v) { *sb = (unsigned)tid; *sw = want - above; *sc = v; }
    __syncthreads();
}

// ---------------------------------------------------------------------------
// Single kernel. Block 0 builds the compacted whitelist, releases g_wl_ready.
// Every block: cheap coalesced pivot (4th-largest warp-max of 256 samples),
// one float4 streaming pass filtering candidates > pivot, exact rank-select
// among candidates (histogram fallback keeps exactness for any input),
// whitelist maxes / pos bits / union max, epilogue, last-block mean.
// ---------------------------------------------------------------------------
__global__ void __launch_bounds__(NTHR, 8)
row_kernel(const float* __restrict__ x, const float* __restrict__ y,
           const void* __restrict__ wlraw, float* __restrict__ out) {
    __shared__ float    s_cand[CAP];              // candidates | fallback hist | mean buf
    __shared__ unsigned s_wsum[NTHR / 32];
    __shared__ float    s_fw[NTHR / 32];
    __shared__ unsigned s_bin, s_want, s_cnt;
    __shared__ unsigned s_ncand;
    __shared__ float    s_self;
    __shared__ int      s_fl[4];
    __shared__ float    s_lmax[NTHR / 32][NL];
    __shared__ float    s_un[NTHR / 32];
    __shared__ unsigned s_pb[NTHR / 32];
    __shared__ int      s_last;

    const int b   = blockIdx.x;
    const int tid = threadIdx.x;
    const float* xr = x + (size_t)b * NC;
    const float* yr = y + (size_t)b * NC;

    // ================= block 0: build whitelist, then release ==============
    if (b == 0) {
        if (tid < 4) s_fl[tid] = 0;
        __syncthreads();
        const int NQ = (NL * NC) / 4;
        const int*   ip = (const int*)wlraw;
        const float* fp = (const float*)wlraw;
        for (int i = tid; i < NQ; i += NTHR) {
            int v = ip[i];
            float f = fp[i];
            if (v != 0 && v != 1)          s_fl[0] = 1;
            if (!(f == 0.0f || f == 1.0f)) s_fl[2] = 1;
            if (f == 1.0f)                 s_fl[3] = 1;
        }
        __syncthreads();
        const int mode = (!s_fl[2] && s_fl[3]) ? 2 : (!s_fl[0] ? 1 : 0);  // f32/i32/u8
        const unsigned char* up = (const unsigned char*)wlraw;
        for (int c = tid; c < NC; c += NTHR) {
            unsigned m = 0;
#pragma unroll
            for (int l = 0; l < NL; ++l) {
                bool on;
                if      (mode == 2) on = (fp[l * NC + c] != 0.0f);
                else if (mode == 1) on = (ip[l * NC + c] != 0);
                else                on = (up[l * NC + c] != 0);
                if (on) m |= (1u << l);
            }
            if (m) {
                int p = atomicAdd(&g_wl_count, 1);
                g_wl_idx[p]  = c;
                g_wl_mask[p] = (unsigned char)m;
            }
        }
        __syncthreads();
        if (tid == 0) { __threadfence(); atomicExch(&g_wl_ready, 1); }
    }

    // ================= pivot: coalesced 256 samples, 1 barrier =============
    {
        float smp = __ldg(xr + 4672 + tid);       // contiguous chunk, coalesced
#pragma unroll
        for (int s = 16; s > 0; s >>= 1)
            smp = fmaxf(smp, __shfl_xor_sync(0xffffffffu, smp, s));
        if ((tid & 31) == 0) s_fw[tid >> 5] = smp;
        if (tid == 0) s_ncand = 0;
    }
    __syncthreads();
    float pivot;
    {
        float a[NTHR / 32];
#pragma unroll
        for (int i = 0; i < NTHR / 32; ++i) a[i] = s_fw[i];
        float mx = 0.0f;
#pragma unroll
        for (int k = 0; k < 4; ++k) {             // 4th-largest of 8 warp maxes
            mx = a[0];
#pragma unroll
            for (int i = 1; i < NTHR / 32; ++i) mx = fmaxf(mx, a[i]);
            if (k < 3) {
#pragma unroll
                for (int i = 0; i < NTHR / 32; ++i)
                    if (a[i] == mx) a[i] = -INFINITY;
            }
        }
        pivot = mx;
    }

    // ================= fused stream: float4 + candidate filter ============
    const int a0   = (-b) & 3;                    // peel to 16B alignment
    const int n4   = (NC - a0) >> 2;
    const int tcnt = (NC - a0) & 3;
    const float4* xr4 = (const float4*)(xr + a0);

    if (tid < a0) {                               // head peel (<=3)
        float v = __ldg(xr + tid);
        if (v > pivot) {
            unsigned p = atomicAdd(&s_ncand, 1u);
            if (p < CAP) s_cand[p] = v;
        }
    }
    if (tid < tcnt) {                             // tail peel (<=3)
        float v = __ldg(xr + a0 + 4 * n4 + tid);
        if (v > pivot) {
            unsigned p = atomicAdd(&s_ncand, 1u);
            if (p < CAP) s_cand[p] = v;
        }
    }
    for (int base = 0; base < n4; base += NTHR * 4) {
        float4 q[4];
        bool   vb[4];
#pragma unroll
        for (int u = 0; u < 4; ++u) {
            const int j = base + u * NTHR + tid;
            vb[u] = (j < n4);
            if (vb[u]) q[u] = __ldg(xr4 + j);
        }
#pragma unroll
        for (int u = 0; u < 4; ++u) {
            if (!vb[u]) continue;
            const float vv[4] = {q[u].x, q[u].y, q[u].z, q[u].w};
#pragma unroll
            for (int e = 0; e < 4; ++e) {
                if (vv[e] > pivot) {
                    unsigned p = atomicAdd(&s_ncand, 1u);
                    if (p < CAP) s_cand[p] = vv[e];
                }
            }
        }
    }
    __syncthreads();

    // ================= exact 11th-largest ==================================
    float x11;
    const unsigned nc0 = s_ncand;
    if (nc0 >= 11u && nc0 <= CAP) {
        // candidates all > pivot, and >=11 of them -> they contain the top-11
        const int n = (int)nc0;
        for (int i = tid; i < n; i += NTHR) {
            const float kk = s_cand[i];
            int gt = 0, ge = 0;
            for (int j = 0; j < n; ++j) {
                const float u = s_cand[j];
                gt += (u > kk);
                ge += (u >= kk);
            }
            if (gt < 11 && 11 <= ge) s_self = kk;
        }
        __syncthreads();
        x11 = s_self;
    } else {
        // ---------- fallback: exact histogram select (adversarial only) ----
        unsigned* s_hist = (unsigned*)s_cand;
        __syncthreads();
#pragma unroll
        for (int i = 0; i < CAP / NTHR; ++i) s_hist[tid + i * NTHR] = 0;
        __syncthreads();
        for (int c = tid; c < NC; c += NTHR) {
            const unsigned key = f2k(__float_as_uint(__ldg(xr + c)));
            atomicAdd(&s_hist[key >> 21], 1u);
        }
        __syncthreads();
        unsigned want = 11;
        pick8(s_hist, s_wsum, &s_bin, &s_want, &s_cnt, want, tid);
        unsigned prefix = s_bin;
        int      pbits  = 11;
        unsigned cnt    = s_cnt;
        want = s_want;
        __syncthreads();
        while (cnt > CAP && pbits < 32) {
            const int nb = (32 - pbits < 8) ? (32 - pbits) : 8;
            if (tid < (1 << nb)) s_hist[tid] = 0;
            __syncthreads();
            for (int c = tid; c < NC; c += NTHR) {
                const unsigned key = f2k(__float_as_uint(__ldg(xr + c)));
                if ((key >> (32 - pbits)) == prefix)
                    atomicAdd(&s_hist[(key >> (32 - pbits - nb)) & ((1u << nb) - 1u)], 1u);
            }
            __syncthreads();
            pick1(s_hist, 1 << nb, s_wsum, &s_bin, &s_want, &s_cnt, want, tid);
            prefix = (prefix << nb) | s_bin;
            pbits += nb;
            cnt  = s_cnt;
            want = s_want;
            __syncthreads();
        }
        unsigned key11;
        if (pbits >= 32) {
            key11 = prefix;
        } else {
            if (tid == 0) s_ncand = 0;
            __syncthreads();
            for (int c = tid; c < NC; c += NTHR) {
                const unsigned key = f2k(__float_as_uint(__ldg(xr + c)));
                if ((key >> (32 - pbits)) == prefix) {
                    unsigned p = atomicAdd(&s_ncand, 1u);
                    if (p < CAP) s_hist[p] = key;
                }
            }
            __syncthreads();
            const int n = (int)s_ncand;
            for (int i = tid; i < n; i += NTHR) {
                const unsigned kk = s_hist[i];
                unsigned gt = 0, ge = 0;
                for (int j = 0; j < n; ++j) {
                    const unsigned u = s_hist[j];
                    gt += (u > kk);
                    ge += (u >= kk);
                }
                if (gt < want && want <= ge) s_self = k2f(kk);
            }
            __syncthreads();
            key11 = 0;   // unused; s_self already set
            x11 = s_self;
            goto have_x11;
        }
        x11 = k2f(key11);
have_x11: ;
    }

    // ================= wait for whitelist (long since ready) ===============
    if (tid == 0 && b != 0) {
        while (atomicOr(&g_wl_ready, 0) == 0) __nanosleep(64);
        __threadfence();
    }
    __syncthreads();

    // ================= whitelist gather (x from L2, y sparse) ==============
    const int nwl = g_wl_count;
    float lmax[NL];
#pragma unroll
    for (int l = 0; l < NL; ++l) lmax[l] = -1e30f;
    float    unf = -1e30f;
    unsigned pos = 0;

    for (int e = tid; e < nwl; e += NTHR) {
        const int      c  = g_wl_idx[e];
        const unsigned m  = g_wl_mask[e];
        const float    xv = __ldg(xr + c);
        const float    yv = __ldg(yr + c);
        unf = fmaxf(unf, xv);
        if (yv > 0.0f) pos |= m;
#pragma unroll
        for (int l = 0; l < NL; ++l)
            if (m & (1u << l)) lmax[l] = fmaxf(lmax[l], xv);
    }
#pragma unroll
    for (int s = 16; s > 0; s >>= 1) {
#pragma unroll
        for (int l = 0; l < NL; ++l)
            lmax[l] = fmaxf(lmax[l], __shfl_xor_sync(0xffffffffu, lmax[l], s));
        unf = fmaxf(unf, __shfl_xor_sync(0xffffffffu, unf, s));
        pos |= __shfl_xor_sync(0xffffffffu, pos, s);
    }
    const int warp = tid >> 5, lane = tid & 31;
    if (lane == 0) {
#pragma unroll
        for (int l = 0; l < NL; ++l) s_lmax[warp][l] = lmax[l];
        s_un[warp] = unf;
        s_pb[warp] = pos;
    }
    __syncthreads();

    if (tid == 0) {
#pragma unroll
        for (int w = 1; w < NTHR / 32; ++w) {
#pragma unroll
            for (int l = 0; l < NL; ++l) lmax[l] = fmaxf(lmax[l], s_lmax[w][l]);
            unf = fmaxf(unf, s_un[w]);
            pos |= s_pb[w];
        }

        const float thres = fmaxf(sigmoidf_(x11), 0.5f);   // ALPHA_OTHER

        float cx = -1e30f, ix = -1e30f;
#pragma unroll
        for (int l = 0; l < NL; ++l) {
            if (pos & (1u << l)) cx = fmaxf(cx, lmax[l]);
            else                 ix = fmaxf(ix, lmax[l]);
        }

        float x1, x2, coef;
        if (pos) {                                  // any_correct
            x1   = sigmoidf_(cx);
            x2   = fmaxf(sigmoidf_(ix), thres);     // covers any_incorrect branch
            coef = 1.0f;
        } else {
            x1   = thres;
            x2   = sigmoidf_(unf);
            coef = 0.5f;                            // 1 - ALPHA
        }
        const float d    = x2 - x1 + 0.1f;          // ALPHA1
        const float rank = (d > 0.0f ? 2.0f : 1.0f) * sigmoidf_(10.0f * d);

        g_row_val[b] = coef * rank;
        __threadfence();
        const int t = atomicAdd(&g_done, 1);
        s_last = (t == BATCH - 1);
    }
    __syncthreads();

    // ================= last block: mean + state reset ======================
    if (s_last) {
        float* s_red = s_cand;
        float acc = 0.0f;
        for (int i = tid; i < BATCH; i += NTHR) acc += g_row_val[i];
        s_red[tid] = acc;
        __syncthreads();
        for (int off = NTHR / 2; off > 0; off >>= 1) {
            if (tid < off) s_red[tid] += s_red[tid + off];
            __syncthreads();
        }
        if (tid == 0) {
            out[0]     = s_red[0] * (1.0f / (float)BATCH);
            g_done     = 0;
            g_wl_count = 0;
            g_wl_ready = 0;
        }
    }
}

extern "C" void kernel_launch(void* const* d_in, const int* in_sizes, int n_in,
                              void* d_out, int out_size) {
    const float* x  = (const float*)d_in[0];
    const float* y  = (const float*)d_in[1];
    // d_in[2] = y_neg: never affects the result, never read.
    const void*  wl = d_in[3];

    row_kernel<<<BATCH, NTHR>>>(x, y, wl, (float*)d_out);
}

// round 10
// speedup vs baseline: 1.9129x; 1.9129x over previous
#include <cuda_runtime.h>
#include <math.h>

#define BATCH 2048
#define NC    9605
#define NL    8
#define MAXWL 512
#define NTHR  256
#define WLB   32
#define NCAND (3 * NTHR)   // 768 per-thread top-3 union
#define CAP   2048         // fallback histogram bins / candidate cap

__device__ int           g_wl_count;   // 0-init; reset by last row block
__device__ int           g_wl_idx[MAXWL];
__device__ unsigned char g_wl_mask[MAXWL];
__device__ float         g_row_val[BATCH];
__device__ int           g_done;       // 0-init; reset by last row block

__device__ __forceinline__ float sigmoidf_(float v) {
    return 1.0f / (1.0f + expf(-v));   // v = -1e30 -> 0 (correct)
}
__device__ __forceinline__ unsigned f2k(unsigned u) {          // monotone float->uint
    return (u & 0x80000000u) ? ~u : (u | 0x80000000u);
}
__device__ __forceinline__ float k2f(unsigned k) {
    return (k & 0x80000000u) ? __uint_as_float(k ^ 0x80000000u)
                             : __uint_as_float(~k);
}
// branchless sorted top-3 insert (6 ops, all fma/alu pipe, no branches)
__device__ __forceinline__ void top3_ins(float v, float& t0, float& t1, float& t2) {
    float m0  = fmaxf(t0, v);
    float mn0 = fminf(t0, v);
    float m1  = fmaxf(t1, mn0);
    float mn1 = fminf(t1, mn0);
    t2 = fmaxf(t2, mn1);
    t0 = m0; t1 = m1;
}

// pick8: suffix-select over 2048 bins (thread t owns bins [8t,8t+8)). (fallback)
__device__ __forceinline__ void pick8(const unsigned* __restrict__ hist,
                                      unsigned* __restrict__ wsum,
                                      unsigned* __restrict__ sb,
                                      unsigned* __restrict__ sw,
                                      unsigned* __restrict__ sc,
                                      unsigned want, int tid) {
    unsigned v[8];
    unsigned tot = 0;
#pragma unroll
    for (int i = 0; i < 8; ++i) { v[i] = hist[tid * 8 + i]; tot += v[i]; }
    unsigned incl = tot;
#pragma unroll
    for (int d = 1; d < 32; d <<= 1) {
        unsigned n = __shfl_down_sync(0xffffffffu, incl, d);
        if ((tid & 31) + d < 32) incl += n;
    }
    if ((tid & 31) == 0) wsum[tid >> 5] = incl;
    __syncthreads();
    unsigned above = incl - tot;
#pragma unroll
    for (int w = 0; w < NTHR / 32; ++w)
        if (w > (tid >> 5)) above += wsum[w];
    unsigned suf = above;
#pragma unroll
    for (int j = 7; j >= 0; --j) {
        unsigned nsuf = suf + v[j];
        if (suf < want && want <= nsuf) {
            *sb = (unsigned)(tid * 8 + j); *sw = want - suf; *sc = v[j];
        }
        suf = nsuf;
    }
    __syncthreads();
}

// pick1: suffix-select over <=256 bins (thread t owns bin t).
__device__ __forceinline__ void pick1(const unsigned* __restrict__ hist, int nbins,
                                      unsigned* __restrict__ wsum,
                                      unsigned* __restrict__ sb,
                                      unsigned* __restrict__ sw,
                                      unsigned* __restrict__ sc,
                                      unsigned want, int tid) {
    unsigned v = (tid < nbins) ? hist[tid] : 0u;
    unsigned incl = v;
#pragma unroll
    for (int d = 1; d < 32; d <<= 1) {
        unsigned n = __shfl_down_sync(0xffffffffu, incl, d);
        if ((tid & 31) + d < 32) incl += n;
    }
    if ((tid & 31) == 0) wsum[tid >> 5] = incl;
    __syncthreads();
    unsigned above = incl - v;
#pragma unroll
    for (int w = 0; w < NTHR / 32; ++w)
        if (w > (tid >> 5)) above += wsum[w];
    if (above < want && want <= above + v) { *sb = (unsigned)tid; *sw = want - above; *sc = v; }
    __syncthreads();
}

// ---------------------------------------------------------------------------
// Kernel 1: dtype-sniffed whitelist compaction (bool may arrive f32/i32/u8).
// ---------------------------------------------------------------------------
__global__ void __launch_bounds__(NTHR) build_wl_kernel(const void* __restrict__ wlraw) {
    __shared__ int fl[4];
    const int tid = threadIdx.x;
    if (tid < 4) fl[tid] = 0;
    __syncthreads();
    const int NQ = (NL * NC) / 4;
    const int*   ip = (const int*)wlraw;
    const float* fp = (const float*)wlraw;
    for (int i = tid; i < NQ; i += NTHR) {
        int v = ip[i];
        float f = fp[i];
        if (v != 0 && v != 1)          fl[0] = 1;
        if (!(f == 0.0f || f == 1.0f)) fl[2] = 1;
        if (f == 1.0f)                 fl[3] = 1;
    }
    __syncthreads();
    const int mode = (!fl[2] && fl[3]) ? 2 : (!fl[0] ? 1 : 0);  // f32/i32/u8
    const unsigned char* up = (const unsigned char*)wlraw;

    for (int c = blockIdx.x * NTHR + tid; c < NC; c += WLB * NTHR) {
        unsigned m = 0;
#pragma unroll
        for (int l = 0; l < NL; ++l) {
            bool on;
            if      (mode == 2) on = (fp[l * NC + c] != 0.0f);
            else if (mode == 1) on = (ip[l * NC + c] != 0);
            else                on = (up[l * NC + c] != 0);
            if (on) m |= (1u << l);
        }
        if (m) {
            int p = atomicAdd(&g_wl_count, 1);
            g_wl_idx[p]  = c;
            g_wl_mask[p] = (unsigned char)m;
        }
    }
}

// ---------------------------------------------------------------------------
// Kernel 2: one block per row.
//  A) float4 stream + branchless per-thread top-3 (no atomics in hot loop)
//  B) 11th-largest of the 768-value union via 4-level 8-bit radix;
//     validity check (block-max t2 <= selected) guards exactness;
//     full-histogram fallback for the ~1e-5 pathological case
//  C) whitelist maxes / pos bits / union max; epilogue; last-block mean
// ---------------------------------------------------------------------------
__global__ void __launch_bounds__(NTHR, 8)
row_kernel(const float* __restrict__ x, const float* __restrict__ y,
           float* __restrict__ out) {
    __shared__ unsigned s_keys[NCAND];
    __shared__ unsigned s_big[CAP];               // level hists / fallback / mean buf
    __shared__ unsigned s_wsum[NTHR / 32];
    __shared__ float    s_fw[NTHR / 32];
    __shared__ unsigned s_bin, s_want, s_cnt;
    __shared__ unsigned s_ncand, s_selk;
    __shared__ float    s_lmax[NTHR / 32][NL];
    __shared__ float    s_un[NTHR / 32];
    __shared__ unsigned s_pb[NTHR / 32];
    __shared__ int      s_last;

    const int b   = blockIdx.x;
    const int tid = threadIdx.x;
    const float* xr = x + (size_t)b * NC;
    const float* yr = y + (size_t)b * NC;

    // ================= phase A: stream + per-thread top-3 =================
    float t0 = -INFINITY, t1 = -INFINITY, t2 = -INFINITY;

    const int a0   = (-b) & 3;                    // peel to 16B alignment (NC%4==1)
    const int n4   = (NC - a0) >> 2;
    const int tcnt = (NC - a0) & 3;
    const float4* xr4 = (const float4*)(xr + a0);

    if (tid < a0)   top3_ins(__ldg(xr + tid), t0, t1, t2);
    if (tid < tcnt) top3_ins(__ldg(xr + a0 + 4 * n4 + tid), t0, t1, t2);

    for (int base = 0; base < n4; base += NTHR * 2) {
        float4 q0, q1;
        const int j0 = base + tid;
        const int j1 = base + NTHR + tid;
        const bool v0 = (j0 < n4), v1 = (j1 < n4);
        if (v0) q0 = __ldg(xr4 + j0);
        if (v1) q1 = __ldg(xr4 + j1);
        if (v0) {
            top3_ins(q0.x, t0, t1, t2); top3_ins(q0.y, t0, t1, t2);
            top3_ins(q0.z, t0, t1, t2); top3_ins(q0.w, t0, t1, t2);
        }
        if (v1) {
            top3_ins(q1.x, t0, t1, t2); top3_ins(q1.y, t0, t1, t2);
            top3_ins(q1.z, t0, t1, t2); top3_ins(q1.w, t0, t1, t2);
        }
    }

    // block max of t2 (validity bound) -> s_fw broadcast
    {
        float m = t2;
#pragma unroll
        for (int s = 16; s > 0; s >>= 1)
            m = fmaxf(m, __shfl_xor_sync(0xffffffffu, m, s));
        if ((tid & 31) == 0) s_fw[tid >> 5] = m;
    }
    // dump keys of the 768-union
    s_keys[tid]            = f2k(__float_as_uint(t0));
    s_keys[NTHR + tid]     = f2k(__float_as_uint(t1));
    s_keys[2 * NTHR + tid] = f2k(__float_as_uint(t2));
    __syncthreads();

    float maxt2 = s_fw[0];
#pragma unroll
    for (int w = 1; w < NTHR / 32; ++w) maxt2 = fmaxf(maxt2, s_fw[w]);
    const unsigned maxt2k = f2k(__float_as_uint(maxt2));

    // ================= 4-level radix select over 768 keys ==================
    unsigned prefix = 0, want = 11;
#pragma unroll
    for (int lvl = 0; lvl < 4; ++lvl) {
        const int sh = 24 - 8 * lvl;
        s_big[tid] = 0;
        __syncthreads();
#pragma unroll
        for (int r = 0; r < 3; ++r) {
            const unsigned k = s_keys[r * NTHR + tid];
            const bool ok = (lvl == 0) || ((k >> (sh + 8)) == prefix);
            if (ok) atomicAdd(&s_big[(k >> sh) & 0xFFu], 1u);
        }
        __syncthreads();
        pick1(s_big, 256, s_wsum, &s_bin, &s_want, &s_cnt, want, tid);
        prefix = (prefix << 8) | s_bin;
        want   = s_want;
        __syncthreads();
    }
    unsigned key11 = prefix;                       // 11th largest of the union

    // ================= validity check / exact fallback =====================
    if (maxt2k > key11) {
        // some thread may have discarded a value > key11 -> exact histogram path
        __syncthreads();
#pragma unroll
        for (int i = 0; i < CAP / NTHR; ++i) s_big[tid + i * NTHR] = 0;
        __syncthreads();
        for (int c = tid; c < NC; c += NTHR) {
            const unsigned key = f2k(__float_as_uint(__ldg(xr + c)));
            atomicAdd(&s_big[key >> 21], 1u);
        }
        __syncthreads();
        want = 11;
        pick8(s_big, s_wsum, &s_bin, &s_want, &s_cnt, want, tid);
        unsigned pfx   = s_bin;
        int      pbits = 11;
        unsigned cnt   = s_cnt;
        want = s_want;
        __syncthreads();
        while (cnt > CAP && pbits < 32) {
            const int nb = (32 - pbits < 8) ? (32 - pbits) : 8;
            if (tid < (1 << nb)) s_big[tid] = 0;
            __syncthreads();
            for (int c = tid; c < NC; c += NTHR) {
                const unsigned key = f2k(__float_as_uint(__ldg(xr + c)));
                if ((key >> (32 - pbits)) == pfx)
                    atomicAdd(&s_big[(key >> (32 - pbits - nb)) & ((1u << nb) - 1u)], 1u);
            }
            __syncthreads();
            pick1(s_big, 1 << nb, s_wsum, &s_bin, &s_want, &s_cnt, want, tid);
            pfx = (pfx << nb) | s_bin;
            pbits += nb;
            cnt  = s_cnt;
            want = s_want;
            __syncthreads();
        }
        if (pbits >= 32) {
            key11 = pfx;
        } else {
            if (tid == 0) s_ncand = 0;
            __syncthreads();
            for (int c = tid; c < NC; c += NTHR) {
                const unsigned key = f2k(__float_as_uint(__ldg(xr + c)));
                if ((key >> (32 - pbits)) == pfx) {
                    unsigned p = atomicAdd(&s_ncand, 1u);
                    if (p < CAP) s_big[p] = key;
                }
            }
            __syncthreads();
            const int n = (int)s_ncand;
            for (int i = tid; i < n; i += NTHR) {
                const unsigned kk = s_big[i];
                unsigned gt = 0, ge = 0;
                for (int j = 0; j < n; ++j) {
                    const unsigned u = s_big[j];
                    gt += (u > kk);
                    ge += (u >= kk);
                }
                if (gt < want && want <= ge) s_selk = kk;
            }
            __syncthreads();
            key11 = s_selk;
        }
    }
    const float x11 = k2f(key11);

    // ================= whitelist gather (x from L2, y sparse) ==============
    const int nwl = g_wl_count;
    float lmax[NL];
#pragma unroll
    for (int l = 0; l < NL; ++l) lmax[l] = -1e30f;
    float    unf = -1e30f;
    unsigned pos = 0;

    for (int e = tid; e < nwl; e += NTHR) {
        const int      c  = g_wl_idx[e];
        const unsigned m  = g_wl_mask[e];
        const float    xv = __ldg(xr + c);
        const float    yv = __ldg(yr + c);
        unf = fmaxf(unf, xv);
        if (yv > 0.0f) pos |= m;
#pragma unroll
        for (int l = 0; l < NL; ++l)
            if (m & (1u << l)) lmax[l] = fmaxf(lmax[l], xv);
    }
#pragma unroll
    for (int s = 16; s > 0; s >>= 1) {
#pragma unroll
        for (int l = 0; l < NL; ++l)
            lmax[l] = fmaxf(lmax[l], __shfl_xor_sync(0xffffffffu, lmax[l], s));
        unf = fmaxf(unf, __shfl_xor_sync(0xffffffffu, unf, s));
        pos |= __shfl_xor_sync(0xffffffffu, pos, s);
    }
    const int warp = tid >> 5, lane = tid & 31;
    if (lane == 0) {
#pragma unroll
        for (int l = 0; l < NL; ++l) s_lmax[warp][l] = lmax[l];
        s_un[warp] = unf;
        s_pb[warp] = pos;
    }
    __syncthreads();

    if (tid == 0) {
#pragma unroll
        for (int w = 1; w < NTHR / 32; ++w) {
#pragma unroll
            for (int l = 0; l < NL; ++l) lmax[l] = fmaxf(lmax[l], s_lmax[w][l]);
            unf = fmaxf(unf, s_un[w]);
            pos |= s_pb[w];
        }

        const float thres = fmaxf(sigmoidf_(x11), 0.5f);   // ALPHA_OTHER

        float cx = -1e30f, ix = -1e30f;
#pragma unroll
        for (int l = 0; l < NL; ++l) {
            if (pos & (1u << l)) cx = fmaxf(cx, lmax[l]);
            else                 ix = fmaxf(ix, lmax[l]);
        }

        float x1, x2, coef;
        if (pos) {                                  // any_correct
            x1   = sigmoidf_(cx);
            x2   = fmaxf(sigmoidf_(ix), thres);     // covers any_incorrect branch
            coef = 1.0f;
        } else {
            x1   = thres;
            x2   = sigmoidf_(unf);
            coef = 0.5f;                            // 1 - ALPHA
        }
        const float d    = x2 - x1 + 0.1f;          // ALPHA1
        const float rank = (d > 0.0f ? 2.0f : 1.0f) * sigmoidf_(10.0f * d);

        g_row_val[b] = coef * rank;
        __threadfence();
        const int t = atomicAdd(&g_done, 1);
        s_last = (t == BATCH - 1);
    }
    __syncthreads();

    // ================= last block: mean + state reset ======================
    if (s_last) {
        float* s_red = (float*)s_big;
        float acc = 0.0f;
        for (int i = tid; i < BATCH; i += NTHR) acc += g_row_val[i];
        s_red[tid] = acc;
        __syncthreads();
        for (int off = NTHR / 2; off > 0; off >>= 1) {
            if (tid < off) s_red[tid] += s_red[tid + off];
            __syncthreads();
        }
        if (tid == 0) {
            out[0]     = s_red[0] * (1.0f / (float)BATCH);
            g_done     = 0;
            g_wl_count = 0;
        }
    }
}

extern "C" void kernel_launch(void* const* d_in, const int* in_sizes, int n_in,
                              void* d_out, int out_size) {
    const float* x  = (const float*)d_in[0];
    const float* y  = (const float*)d_in[1];
    // d_in[2] = y_neg: never affects the result, never read.
    const void*  wl = d_in[3];

    build_wl_kernel<<<WLB, NTHR>>>(wl);
    row_kernel<<<BATCH, NTHR>>>(x, y, (float*)d_out);
}